// round 11
// baseline (speedup 1.0000x reference)
#include <cuda_runtime.h>
#include <cstdint>
#include <cfloat>

// Problem constants
#define QN   512
#define NLIB 262144
#define DDIM 768
#define KSEL 10

// GEMM tiling
#define BM 128
#define BN 128
#define BK 8
#define SA 10          // smem row stride in floats (pad 8 -> 10, conflict-free banks)
#define NSTAGE (DDIM / BK)   // 96

// ---------------- scratch (static device allocations only) ----------------
__device__ float g_d2[(size_t)QN * NLIB];   // 512 MB distance matrix
__device__ float g_xsq[NLIB];
__device__ float g_qsq[QN];

// ---------------- f32x2 helpers ----------------
__device__ __forceinline__ void fma2(unsigned long long& d,
                                     unsigned long long a,
                                     unsigned long long b) {
    asm("fma.rn.f32x2 %0, %1, %2, %0;" : "+l"(d) : "l"(a), "l"(b));
}
__device__ __forceinline__ float2 unpack2(unsigned long long v) {
    float2 r;
    asm("mov.b64 {%0, %1}, %2;" : "=f"(r.x), "=f"(r.y) : "l"(v));
    return r;
}

// ---------------- row squared-norm kernel (warp per row) ----------------
__global__ void rownorm_kernel(const float* __restrict__ x, int rows, int which) {
    int gt = blockIdx.x * blockDim.x + threadIdx.x;
    int w = gt >> 5;
    int lane = gt & 31;
    if (w >= rows) return;
    const float4* p = reinterpret_cast<const float4*>(x + (size_t)w * DDIM);
    float s = 0.f;
#pragma unroll
    for (int i = lane; i < DDIM / 4; i += 32) {
        float4 v = p[i];
        s = fmaf(v.x, v.x, fmaf(v.y, v.y, fmaf(v.z, v.z, fmaf(v.w, v.w, s))));
    }
#pragma unroll
    for (int o = 16; o; o >>= 1) s += __shfl_xor_sync(0xffffffffu, s, o);
    if (lane == 0) {
        if (which) g_xsq[w] = s; else g_qsq[w] = s;
    }
}

// ---------------- fused GEMM -> d2 kernel ----------------
// d2[m][n] = qsq[m] - 2 * <q_m, x_n> + xsq[n]
// 256 threads, 8x8 outputs/thread, f32x2 accumulators packed along K (2 k-parities).
__global__ void __launch_bounds__(256) gemm_d2_kernel(const float* __restrict__ Qm,
                                                      const float* __restrict__ Lm) {
    __shared__ float As[2][BM * SA];
    __shared__ float Bs[2][BN * SA];

    const int tid = threadIdx.x;
    const int tx = tid & 15;        // n-direction lane
    const int ty = tid >> 4;        // m-direction lane
    const int m0 = blockIdx.y * BM;
    const int n0 = blockIdx.x * BN;

    // stage-copy mapping: 256 float4 per tile (128 rows x 8 k), 1 per thread
    const int lrow = tid >> 1;            // 0..127
    const int lk   = (tid & 1) * 4;       // 0 or 4
    const float* Ag = Qm + (size_t)(m0 + lrow) * DDIM + lk;
    const float* Bg = Lm + (size_t)(n0 + lrow) * DDIM + lk;
    const int soff = lrow * SA + lk;

    // stage 0
    {
        float4 pa = *reinterpret_cast<const float4*>(Ag);
        float4 pb = *reinterpret_cast<const float4*>(Bg);
        *reinterpret_cast<float2*>(&As[0][soff])     = make_float2(pa.x, pa.y);
        *reinterpret_cast<float2*>(&As[0][soff + 2]) = make_float2(pa.z, pa.w);
        *reinterpret_cast<float2*>(&Bs[0][soff])     = make_float2(pb.x, pb.y);
        *reinterpret_cast<float2*>(&Bs[0][soff + 2]) = make_float2(pb.z, pb.w);
    }
    __syncthreads();

    unsigned long long acc[8][8];
#pragma unroll
    for (int i = 0; i < 8; ++i)
#pragma unroll
        for (int j = 0; j < 8; ++j) acc[i][j] = 0ull;

    int buf = 0;
#pragma unroll 1
    for (int t = 0; t < NSTAGE; ++t) {
        float4 na, nb;
        const bool more = (t + 1 < NSTAGE);
        if (more) {
            na = *reinterpret_cast<const float4*>(Ag + (t + 1) * BK);
            nb = *reinterpret_cast<const float4*>(Bg + (t + 1) * BK);
        }
        const float* Ab = As[buf];
        const float* Bb = Bs[buf];
#pragma unroll
        for (int kp = 0; kp < BK / 2; ++kp) {
            unsigned long long a[8], b[8];
#pragma unroll
            for (int i = 0; i < 8; ++i)
                a[i] = *reinterpret_cast<const unsigned long long*>(
                    &Ab[(ty + 16 * i) * SA + 2 * kp]);
#pragma unroll
            for (int j = 0; j < 8; ++j)
                b[j] = *reinterpret_cast<const unsigned long long*>(
                    &Bb[(tx + 16 * j) * SA + 2 * kp]);
#pragma unroll
            for (int i = 0; i < 8; ++i)
#pragma unroll
                for (int j = 0; j < 8; ++j) fma2(acc[i][j], a[i], b[j]);
        }
        if (more) {
            const int nxt = buf ^ 1;
            *reinterpret_cast<float2*>(&As[nxt][soff])     = make_float2(na.x, na.y);
            *reinterpret_cast<float2*>(&As[nxt][soff + 2]) = make_float2(na.z, na.w);
            *reinterpret_cast<float2*>(&Bs[nxt][soff])     = make_float2(nb.x, nb.y);
            *reinterpret_cast<float2*>(&Bs[nxt][soff + 2]) = make_float2(nb.z, nb.w);
            __syncthreads();
            buf = nxt;
        }
    }

    // epilogue: add norms, write d2
    float xs[8];
#pragma unroll
    for (int j = 0; j < 8; ++j) xs[j] = g_xsq[n0 + tx + 16 * j];
#pragma unroll
    for (int i = 0; i < 8; ++i) {
        const int m = m0 + ty + 16 * i;
        const float qs = g_qsq[m];
        const size_t rowoff = (size_t)m * NLIB;
#pragma unroll
        for (int j = 0; j < 8; ++j) {
            const int n = n0 + tx + 16 * j;
            float2 c = unpack2(acc[i][j]);
            g_d2[rowoff + n] = fmaf(-2.f, c.x + c.y, qs + xs[j]);
        }
    }
}

// ---------------- top-k kernel: one CTA per query ----------------
__global__ void topk_kernel(float* __restrict__ out, int out_size) {
    const int q = blockIdx.x;
    const int tid = threadIdx.x;             // 256 threads
    const float* row = g_d2 + (size_t)q * NLIB;

    float lv[KSEL];
    int   li[KSEL];
#pragma unroll
    for (int s = 0; s < KSEL; ++s) { lv[s] = FLT_MAX; li[s] = 0x7FFFFFFF; }
    float th = FLT_MAX;

    for (int j = tid; j < NLIB; j += 256) {
        float v = row[j];
        if (v < th) {
            int p = KSEL - 1;
            while (p > 0 && lv[p - 1] > v) {
                lv[p] = lv[p - 1]; li[p] = li[p - 1]; --p;
            }
            lv[p] = v; li[p] = j;
            th = lv[KSEL - 1];
        }
    }

    __shared__ float sv[256 * KSEL];
    __shared__ int   si[256 * KSEL];
    __shared__ float rv[256];
    __shared__ int   ri[256];
    __shared__ int   rp[256];
#pragma unroll
    for (int s = 0; s < KSEL; ++s) {
        sv[tid * KSEL + s] = lv[s];
        si[tid * KSEL + s] = li[s];
    }
    __syncthreads();

    for (int r = 0; r < KSEL; ++r) {
        float bv = FLT_MAX; int bi = 0x7FFFFFFF; int bp = tid * KSEL;
#pragma unroll
        for (int s = 0; s < KSEL; ++s) {
            int p = tid * KSEL + s;
            float v = sv[p]; int ix = si[p];
            if (v < bv || (v == bv && ix < bi)) { bv = v; bi = ix; bp = p; }
        }
        rv[tid] = bv; ri[tid] = bi; rp[tid] = bp;
        __syncthreads();
        for (int s = 128; s > 0; s >>= 1) {
            if (tid < s) {
                float v2 = rv[tid + s]; int i2 = ri[tid + s];
                if (v2 < rv[tid] || (v2 == rv[tid] && i2 < ri[tid])) {
                    rv[tid] = v2; ri[tid] = i2; rp[tid] = rp[tid + s];
                }
            }
            __syncthreads();
        }
        if (tid == 0) {
            int o = q * KSEL + r;
            if (o < out_size) out[o] = rv[0];
            int o2 = QN * KSEL + q * KSEL + r;
            if (o2 < out_size) out[o2] = (float)ri[0];
            sv[rp[0]] = FLT_MAX;
            si[rp[0]] = 0x7FFFFFFF;
        }
        __syncthreads();
    }
}

// ---------------- launch ----------------
extern "C" void kernel_launch(void* const* d_in, const int* in_sizes, int n_in,
                              void* d_out, int out_size) {
    const float* query = (const float*)d_in[0];
    const float* lib   = (const float*)d_in[1];
    float* out = (float*)d_out;

    // squared norms
    rownorm_kernel<<<(QN * 32 + 255) / 256, 256>>>(query, QN, 0);
    rownorm_kernel<<<(NLIB * 32 + 255) / 256, 256>>>(lib, NLIB, 1);

    // distance matrix
    dim3 grid(NLIB / BN, QN / BM);
    gemm_d2_kernel<<<grid, 256>>>(query, lib);

    // per-query top-10
    topk_kernel<<<QN, 256>>>(out, out_size);
}

// round 12
// speedup vs baseline: 1.0012x; 1.0012x over previous
#include <cuda_runtime.h>
#include <cstdint>
#include <cfloat>

// Problem constants
#define QN   512
#define NLIB 262144
#define DDIM 768
#define KSEL 10

// GEMM tiling
#define BM 128
#define BN 128
#define BK 8
#define SA 10          // smem row stride in floats (pad 8 -> 10, conflict-free banks)
#define NSTAGE (DDIM / BK)   // 96

// ---------------- scratch (static device allocations only) ----------------
__device__ float g_d2[(size_t)QN * NLIB];   // 512 MB distance matrix
__device__ float g_xsq[NLIB];
__device__ float g_qsq[QN];

// ---------------- f32x2 helpers ----------------
__device__ __forceinline__ void fma2(unsigned long long& d,
                                     unsigned long long a,
                                     unsigned long long b) {
    asm("fma.rn.f32x2 %0, %1, %2, %0;" : "+l"(d) : "l"(a), "l"(b));
}
__device__ __forceinline__ float2 unpack2(unsigned long long v) {
    float2 r;
    asm("mov.b64 {%0, %1}, %2;" : "=f"(r.x), "=f"(r.y) : "l"(v));
    return r;
}

// ---------------- row squared-norm kernel (warp per row) ----------------
__global__ void rownorm_kernel(const float* __restrict__ x, int rows, int which) {
    int gt = blockIdx.x * blockDim.x + threadIdx.x;
    int w = gt >> 5;
    int lane = gt & 31;
    if (w >= rows) return;
    const float4* p = reinterpret_cast<const float4*>(x + (size_t)w * DDIM);
    float s = 0.f;
#pragma unroll
    for (int i = lane; i < DDIM / 4; i += 32) {
        float4 v = p[i];
        s = fmaf(v.x, v.x, fmaf(v.y, v.y, fmaf(v.z, v.z, fmaf(v.w, v.w, s))));
    }
#pragma unroll
    for (int o = 16; o; o >>= 1) s += __shfl_xor_sync(0xffffffffu, s, o);
    if (lane == 0) {
        if (which) g_xsq[w] = s; else g_qsq[w] = s;
    }
}

// ---------------- fused GEMM -> d2 kernel ----------------
// d2[m][n] = qsq[m] - 2 * <q_m, x_n> + xsq[n]
// 256 threads, 8x8 outputs/thread, f32x2 accumulators packed along K (2 k-parities).
__global__ void __launch_bounds__(256) gemm_d2_kernel(const float* __restrict__ Qm,
                                                      const float* __restrict__ Lm) {
    __shared__ float As[2][BM * SA];
    __shared__ float Bs[2][BN * SA];

    const int tid = threadIdx.x;
    const int tx = tid & 15;        // n-direction lane
    const int ty = tid >> 4;        // m-direction lane
    const int m0 = blockIdx.y * BM;
    const int n0 = blockIdx.x * BN;

    // stage-copy mapping: 256 float4 per tile (128 rows x 8 k), 1 per thread
    const int lrow = tid >> 1;            // 0..127
    const int lk   = (tid & 1) * 4;       // 0 or 4
    const float* Ag = Qm + (size_t)(m0 + lrow) * DDIM + lk;
    const float* Bg = Lm + (size_t)(n0 + lrow) * DDIM + lk;
    const int soff = lrow * SA + lk;

    // stage 0
    {
        float4 pa = *reinterpret_cast<const float4*>(Ag);
        float4 pb = *reinterpret_cast<const float4*>(Bg);
        *reinterpret_cast<float2*>(&As[0][soff])     = make_float2(pa.x, pa.y);
        *reinterpret_cast<float2*>(&As[0][soff + 2]) = make_float2(pa.z, pa.w);
        *reinterpret_cast<float2*>(&Bs[0][soff])     = make_float2(pb.x, pb.y);
        *reinterpret_cast<float2*>(&Bs[0][soff + 2]) = make_float2(pb.z, pb.w);
    }
    __syncthreads();

    unsigned long long acc[8][8];
#pragma unroll
    for (int i = 0; i < 8; ++i)
#pragma unroll
        for (int j = 0; j < 8; ++j) acc[i][j] = 0ull;

    int buf = 0;
#pragma unroll 1
    for (int t = 0; t < NSTAGE; ++t) {
        float4 na, nb;
        const bool more = (t + 1 < NSTAGE);
        if (more) {
            na = *reinterpret_cast<const float4*>(Ag + (t + 1) * BK);
            nb = *reinterpret_cast<const float4*>(Bg + (t + 1) * BK);
        }
        const float* Ab = As[buf];
        const float* Bb = Bs[buf];
#pragma unroll
        for (int kp = 0; kp < BK / 2; ++kp) {
            unsigned long long a[8], b[8];
#pragma unroll
            for (int i = 0; i < 8; ++i)
                a[i] = *reinterpret_cast<const unsigned long long*>(
                    &Ab[(ty + 16 * i) * SA + 2 * kp]);
#pragma unroll
            for (int j = 0; j < 8; ++j)
                b[j] = *reinterpret_cast<const unsigned long long*>(
                    &Bb[(tx + 16 * j) * SA + 2 * kp]);
#pragma unroll
            for (int i = 0; i < 8; ++i)
#pragma unroll
                for (int j = 0; j < 8; ++j) fma2(acc[i][j], a[i], b[j]);
        }
        if (more) {
            const int nxt = buf ^ 1;
            *reinterpret_cast<float2*>(&As[nxt][soff])     = make_float2(na.x, na.y);
            *reinterpret_cast<float2*>(&As[nxt][soff + 2]) = make_float2(na.z, na.w);
            *reinterpret_cast<float2*>(&Bs[nxt][soff])     = make_float2(nb.x, nb.y);
            *reinterpret_cast<float2*>(&Bs[nxt][soff + 2]) = make_float2(nb.z, nb.w);
            __syncthreads();
            buf = nxt;
        }
    }

    // epilogue: add norms, write d2
    float xs[8];
#pragma unroll
    for (int j = 0; j < 8; ++j) xs[j] = g_xsq[n0 + tx + 16 * j];
#pragma unroll
    for (int i = 0; i < 8; ++i) {
        const int m = m0 + ty + 16 * i;
        const float qs = g_qsq[m];
        const size_t rowoff = (size_t)m * NLIB;
#pragma unroll
        for (int j = 0; j < 8; ++j) {
            const int n = n0 + tx + 16 * j;
            float2 c = unpack2(acc[i][j]);
            g_d2[rowoff + n] = fmaf(-2.f, c.x + c.y, qs + xs[j]);
        }
    }
}

// ---------------- top-k kernel: one CTA per query ----------------
__global__ void topk_kernel(float* __restrict__ out, int out_size) {
    const int q = blockIdx.x;
    const int tid = threadIdx.x;             // 256 threads
    const float* row = g_d2 + (size_t)q * NLIB;

    float lv[KSEL];
    int   li[KSEL];
#pragma unroll
    for (int s = 0; s < KSEL; ++s) { lv[s] = FLT_MAX; li[s] = 0x7FFFFFFF; }
    float th = FLT_MAX;

    for (int j = tid; j < NLIB; j += 256) {
        float v = row[j];
        if (v < th) {
            int p = KSEL - 1;
            while (p > 0 && lv[p - 1] > v) {
                lv[p] = lv[p - 1]; li[p] = li[p - 1]; --p;
            }
            lv[p] = v; li[p] = j;
            th = lv[KSEL - 1];
        }
    }

    __shared__ float sv[256 * KSEL];
    __shared__ int   si[256 * KSEL];
    __shared__ float rv[256];
    __shared__ int   ri[256];
    __shared__ int   rp[256];
#pragma unroll
    for (int s = 0; s < KSEL; ++s) {
        sv[tid * KSEL + s] = lv[s];
        si[tid * KSEL + s] = li[s];
    }
    __syncthreads();

    for (int r = 0; r < KSEL; ++r) {
        float bv = FLT_MAX; int bi = 0x7FFFFFFF; int bp = tid * KSEL;
#pragma unroll
        for (int s = 0; s < KSEL; ++s) {
            int p = tid * KSEL + s;
            float v = sv[p]; int ix = si[p];
            if (v < bv || (v == bv && ix < bi)) { bv = v; bi = ix; bp = p; }
        }
        rv[tid] = bv; ri[tid] = bi; rp[tid] = bp;
        __syncthreads();
        for (int s = 128; s > 0; s >>= 1) {
            if (tid < s) {
                float v2 = rv[tid + s]; int i2 = ri[tid + s];
                if (v2 < rv[tid] || (v2 == rv[tid] && i2 < ri[tid])) {
                    rv[tid] = v2; ri[tid] = i2; rp[tid] = rp[tid + s];
                }
            }
            __syncthreads();
        }
        if (tid == 0) {
            int o = q * KSEL + r;
            if (o < out_size) out[o] = rv[0];
            int o2 = QN * KSEL + q * KSEL + r;
            if (o2 < out_size) out[o2] = (float)ri[0];
            sv[rp[0]] = FLT_MAX;
            si[rp[0]] = 0x7FFFFFFF;
        }
        __syncthreads();
    }
}

// ---------------- launch ----------------
extern "C" void kernel_launch(void* const* d_in, const int* in_sizes, int n_in,
                              void* d_out, int out_size) {
    const float* query = (const float*)d_in[0];
    const float* lib   = (const float*)d_in[1];
    float* out = (float*)d_out;

    // squared norms
    rownorm_kernel<<<(QN * 32 + 255) / 256, 256>>>(query, QN, 0);
    rownorm_kernel<<<(NLIB * 32 + 255) / 256, 256>>>(lib, NLIB, 1);

    // distance matrix
    dim3 grid(NLIB / BN, QN / BM);
    gemm_d2_kernel<<<grid, 256>>>(query, lib);

    // per-query top-10
    topk_kernel<<<QN, 256>>>(out, out_size);
}

// round 13
// speedup vs baseline: 1.0024x; 1.0012x over previous
#include <cuda_runtime.h>
#include <cstdint>
#include <cfloat>

// Problem constants
#define QN   512
#define NLIB 262144
#define DDIM 768
#define KSEL 10

// GEMM tiling
#define BM 128
#define BN 128
#define BK 8
#define SA 10          // smem row stride in floats (pad 8 -> 10, conflict-free banks)
#define NSTAGE (DDIM / BK)   // 96

// ---------------- scratch (static device allocations only) ----------------
__device__ float g_d2[(size_t)QN * NLIB];   // 512 MB distance matrix
__device__ float g_xsq[NLIB];
__device__ float g_qsq[QN];

// ---------------- f32x2 helpers ----------------
__device__ __forceinline__ void fma2(unsigned long long& d,
                                     unsigned long long a,
                                     unsigned long long b) {
    asm("fma.rn.f32x2 %0, %1, %2, %0;" : "+l"(d) : "l"(a), "l"(b));
}
__device__ __forceinline__ float2 unpack2(unsigned long long v) {
    float2 r;
    asm("mov.b64 {%0, %1}, %2;" : "=f"(r.x), "=f"(r.y) : "l"(v));
    return r;
}

// ---------------- row squared-norm kernel (warp per row) ----------------
__global__ void rownorm_kernel(const float* __restrict__ x, int rows, int which) {
    int gt = blockIdx.x * blockDim.x + threadIdx.x;
    int w = gt >> 5;
    int lane = gt & 31;
    if (w >= rows) return;
    const float4* p = reinterpret_cast<const float4*>(x + (size_t)w * DDIM);
    float s = 0.f;
#pragma unroll
    for (int i = lane; i < DDIM / 4; i += 32) {
        float4 v = p[i];
        s = fmaf(v.x, v.x, fmaf(v.y, v.y, fmaf(v.z, v.z, fmaf(v.w, v.w, s))));
    }
#pragma unroll
    for (int o = 16; o; o >>= 1) s += __shfl_xor_sync(0xffffffffu, s, o);
    if (lane == 0) {
        if (which) g_xsq[w] = s; else g_qsq[w] = s;
    }
}

// ---------------- fused GEMM -> d2 kernel ----------------
// d2[m][n] = qsq[m] - 2 * <q_m, x_n> + xsq[n]
// 256 threads, 8x8 outputs/thread, f32x2 accumulators packed along K (2 k-parities).
__global__ void __launch_bounds__(256) gemm_d2_kernel(const float* __restrict__ Qm,
                                                      const float* __restrict__ Lm) {
    __shared__ float As[2][BM * SA];
    __shared__ float Bs[2][BN * SA];

    const int tid = threadIdx.x;
    const int tx = tid & 15;        // n-direction lane
    const int ty = tid >> 4;        // m-direction lane
    const int m0 = blockIdx.y * BM;
    const int n0 = blockIdx.x * BN;

    // stage-copy mapping: 256 float4 per tile (128 rows x 8 k), 1 per thread
    const int lrow = tid >> 1;            // 0..127
    const int lk   = (tid & 1) * 4;       // 0 or 4
    const float* Ag = Qm + (size_t)(m0 + lrow) * DDIM + lk;
    const float* Bg = Lm + (size_t)(n0 + lrow) * DDIM + lk;
    const int soff = lrow * SA + lk;

    // stage 0
    {
        float4 pa = *reinterpret_cast<const float4*>(Ag);
        float4 pb = *reinterpret_cast<const float4*>(Bg);
        *reinterpret_cast<float2*>(&As[0][soff])     = make_float2(pa.x, pa.y);
        *reinterpret_cast<float2*>(&As[0][soff + 2]) = make_float2(pa.z, pa.w);
        *reinterpret_cast<float2*>(&Bs[0][soff])     = make_float2(pb.x, pb.y);
        *reinterpret_cast<float2*>(&Bs[0][soff + 2]) = make_float2(pb.z, pb.w);
    }
    __syncthreads();

    unsigned long long acc[8][8];
#pragma unroll
    for (int i = 0; i < 8; ++i)
#pragma unroll
        for (int j = 0; j < 8; ++j) acc[i][j] = 0ull;

    int buf = 0;
#pragma unroll 1
    for (int t = 0; t < NSTAGE; ++t) {
        float4 na, nb;
        const bool more = (t + 1 < NSTAGE);
        if (more) {
            na = *reinterpret_cast<const float4*>(Ag + (t + 1) * BK);
            nb = *reinterpret_cast<const float4*>(Bg + (t + 1) * BK);
        }
        const float* Ab = As[buf];
        const float* Bb = Bs[buf];
#pragma unroll
        for (int kp = 0; kp < BK / 2; ++kp) {
            unsigned long long a[8], b[8];
#pragma unroll
            for (int i = 0; i < 8; ++i)
                a[i] = *reinterpret_cast<const unsigned long long*>(
                    &Ab[(ty + 16 * i) * SA + 2 * kp]);
#pragma unroll
            for (int j = 0; j < 8; ++j)
                b[j] = *reinterpret_cast<const unsigned long long*>(
                    &Bb[(tx + 16 * j) * SA + 2 * kp]);
#pragma unroll
            for (int i = 0; i < 8; ++i)
#pragma unroll
                for (int j = 0; j < 8; ++j) fma2(acc[i][j], a[i], b[j]);
        }
        if (more) {
            const int nxt = buf ^ 1;
            *reinterpret_cast<float2*>(&As[nxt][soff])     = make_float2(na.x, na.y);
            *reinterpret_cast<float2*>(&As[nxt][soff + 2]) = make_float2(na.z, na.w);
            *reinterpret_cast<float2*>(&Bs[nxt][soff])     = make_float2(nb.x, nb.y);
            *reinterpret_cast<float2*>(&Bs[nxt][soff + 2]) = make_float2(nb.z, nb.w);
            __syncthreads();
            buf = nxt;
        }
    }

    // epilogue: add norms, write d2
    float xs[8];
#pragma unroll
    for (int j = 0; j < 8; ++j) xs[j] = g_xsq[n0 + tx + 16 * j];
#pragma unroll
    for (int i = 0; i < 8; ++i) {
        const int m = m0 + ty + 16 * i;
        const float qs = g_qsq[m];
        const size_t rowoff = (size_t)m * NLIB;
#pragma unroll
        for (int j = 0; j < 8; ++j) {
            const int n = n0 + tx + 16 * j;
            float2 c = unpack2(acc[i][j]);
            g_d2[rowoff + n] = fmaf(-2.f, c.x + c.y, qs + xs[j]);
        }
    }
}

// ---------------- top-k kernel: one CTA per query ----------------
__global__ void topk_kernel(float* __restrict__ out, int out_size) {
    const int q = blockIdx.x;
    const int tid = threadIdx.x;             // 256 threads
    const float* row = g_d2 + (size_t)q * NLIB;

    float lv[KSEL];
    int   li[KSEL];
#pragma unroll
    for (int s = 0; s < KSEL; ++s) { lv[s] = FLT_MAX; li[s] = 0x7FFFFFFF; }
    float th = FLT_MAX;

    for (int j = tid; j < NLIB; j += 256) {
        float v = row[j];
        if (v < th) {
            int p = KSEL - 1;
            while (p > 0 && lv[p - 1] > v) {
                lv[p] = lv[p - 1]; li[p] = li[p - 1]; --p;
            }
            lv[p] = v; li[p] = j;
            th = lv[KSEL - 1];
        }
    }

    __shared__ float sv[256 * KSEL];
    __shared__ int   si[256 * KSEL];
    __shared__ float rv[256];
    __shared__ int   ri[256];
    __shared__ int   rp[256];
#pragma unroll
    for (int s = 0; s < KSEL; ++s) {
        sv[tid * KSEL + s] = lv[s];
        si[tid * KSEL + s] = li[s];
    }
    __syncthreads();

    for (int r = 0; r < KSEL; ++r) {
        float bv = FLT_MAX; int bi = 0x7FFFFFFF; int bp = tid * KSEL;
#pragma unroll
        for (int s = 0; s < KSEL; ++s) {
            int p = tid * KSEL + s;
            float v = sv[p]; int ix = si[p];
            if (v < bv || (v == bv && ix < bi)) { bv = v; bi = ix; bp = p; }
        }
        rv[tid] = bv; ri[tid] = bi; rp[tid] = bp;
        __syncthreads();
        for (int s = 128; s > 0; s >>= 1) {
            if (tid < s) {
                float v2 = rv[tid + s]; int i2 = ri[tid + s];
                if (v2 < rv[tid] || (v2 == rv[tid] && i2 < ri[tid])) {
                    rv[tid] = v2; ri[tid] = i2; rp[tid] = rp[tid + s];
                }
            }
            __syncthreads();
        }
        if (tid == 0) {
            int o = q * KSEL + r;
            if (o < out_size) out[o] = rv[0];
            int o2 = QN * KSEL + q * KSEL + r;
            if (o2 < out_size) out[o2] = (float)ri[0];
            sv[rp[0]] = FLT_MAX;
            si[rp[0]] = 0x7FFFFFFF;
        }
        __syncthreads();
    }
}

// ---------------- launch ----------------
extern "C" void kernel_launch(void* const* d_in, const int* in_sizes, int n_in,
                              void* d_out, int out_size) {
    const float* query = (const float*)d_in[0];
    const float* lib   = (const float*)d_in[1];
    float* out = (float*)d_out;

    // squared norms
    rownorm_kernel<<<(QN * 32 + 255) / 256, 256>>>(query, QN, 0);
    rownorm_kernel<<<(NLIB * 32 + 255) / 256, 256>>>(lib, NLIB, 1);

    // distance matrix
    dim3 grid(NLIB / BN, QN / BM);
    gemm_d2_kernel<<<grid, 256>>>(query, lib);

    // per-query top-10
    topk_kernel<<<QN, 256>>>(out, out_size);
}

// round 16
// speedup vs baseline: 1.5376x; 1.5339x over previous
#include <cuda_runtime.h>
#include <cuda_bf16.h>
#include <cstdint>
#include <cfloat>

// Problem constants
#define QN    512
#define NLIB  262144
#define DDIM  768
#define KOUT  10
#define KCAND 16

// GEMM tiling
#define TM 128
#define TN 128
#define KCH 32                       // bf16 k per chunk
#define NCHUNK (DDIM / KCH)          // 24
#define ROWB 80                      // smem row stride bytes (32 bf16 -> 80B pad)
#define HALF_TILE (64 * ROWB)        // 5120
#define MAT_BYTES (128 * ROWB)       // 10240
#define STAGE_BYTES (2 * MAT_BYTES)  // 20480 (A + B)
#define NSTG 4
#define SMEM_BYTES (NSTG * STAGE_BYTES)  // 81920

// ---------------- scratch ----------------
__device__ float g_d2[(size_t)QN * NLIB];                       // 512 MB
__device__ __align__(16) __nv_bfloat16 g_libb[(size_t)NLIB * DDIM]; // 384 MB
__device__ __align__(16) __nv_bfloat16 g_qb[(size_t)QN * DDIM];
__device__ float g_xsq[NLIB];
__device__ float g_qsq[QN];
__device__ int   g_cand[QN * KCAND];

// ---------------- PTX helpers ----------------
__device__ __forceinline__ uint32_t smem_u32(const void* p) {
    uint32_t a;
    asm("{ .reg .u64 t; cvta.to.shared.u64 t, %1; cvt.u32.u64 %0, t; }"
        : "=r"(a) : "l"(p));
    return a;
}
__device__ __forceinline__ void cp16(uint32_t s, const void* g) {
    asm volatile("cp.async.cg.shared.global [%0], [%1], 16;" :: "r"(s), "l"(g));
}
__device__ __forceinline__ void cp_commit() {
    asm volatile("cp.async.commit_group;" ::: "memory");
}
template <int N>
__device__ __forceinline__ void cp_wait() {
    asm volatile("cp.async.wait_group %0;" :: "n"(N) : "memory");
}
__device__ __forceinline__ void ldm4(uint32_t& r0, uint32_t& r1, uint32_t& r2,
                                     uint32_t& r3, uint32_t a) {
    asm volatile("ldmatrix.sync.aligned.m8n8.x4.shared.b16 {%0,%1,%2,%3}, [%4];"
                 : "=r"(r0), "=r"(r1), "=r"(r2), "=r"(r3) : "r"(a));
}
__device__ __forceinline__ void mma16816(float* c, const uint32_t* a, const uint32_t* b) {
    asm volatile(
        "mma.sync.aligned.m16n8k16.row.col.f32.bf16.bf16.f32 "
        "{%0,%1,%2,%3}, {%4,%5,%6,%7}, {%8,%9}, {%0,%1,%2,%3};"
        : "+f"(c[0]), "+f"(c[1]), "+f"(c[2]), "+f"(c[3])
        : "r"(a[0]), "r"(a[1]), "r"(a[2]), "r"(a[3]), "r"(b[0]), "r"(b[1]));
}
// pack (x low element, y high element) into bf16x2
__device__ __forceinline__ uint32_t pack2(float x, float y) {
    uint32_t r;
    asm("cvt.rn.bf16x2.f32 %0, %1, %2;" : "=r"(r) : "f"(y), "f"(x));
    return r;
}

// ---------------- fused convert(fp32->bf16) + row squared-norm ----------------
__global__ void convert_kernel(const float* __restrict__ x,
                               __nv_bfloat16* __restrict__ xb,
                               float* __restrict__ sq, int rows) {
    int gt = blockIdx.x * blockDim.x + threadIdx.x;
    int w = gt >> 5;
    int lane = gt & 31;
    if (w >= rows) return;
    const float4* p = reinterpret_cast<const float4*>(x + (size_t)w * DDIM);
    uint4* o = reinterpret_cast<uint4*>(xb + (size_t)w * DDIM);
    float s = 0.f;
#pragma unroll
    for (int i = lane; i < DDIM / 8; i += 32) {
        float4 v0 = p[2 * i];
        float4 v1 = p[2 * i + 1];
        s = fmaf(v0.x, v0.x, fmaf(v0.y, v0.y, fmaf(v0.z, v0.z, fmaf(v0.w, v0.w, s))));
        s = fmaf(v1.x, v1.x, fmaf(v1.y, v1.y, fmaf(v1.z, v1.z, fmaf(v1.w, v1.w, s))));
        uint4 u;
        u.x = pack2(v0.x, v0.y);
        u.y = pack2(v0.z, v0.w);
        u.z = pack2(v1.x, v1.y);
        u.w = pack2(v1.z, v1.w);
        o[i] = u;
    }
#pragma unroll
    for (int off = 16; off; off >>= 1) s += __shfl_xor_sync(0xffffffffu, s, off);
    if (lane == 0) sq[w] = s;
}

// ---------------- bf16 mma.sync GEMM -> approx d2 ----------------
__global__ void __launch_bounds__(256) gemm_kernel() {
    extern __shared__ __align__(16) char dyn_smem[];
    const uint32_t sbase = smem_u32(dyn_smem);

    const int tid  = threadIdx.x;
    const int lane = tid & 31;
    const int warp = tid >> 5;
    const int wm = warp >> 2;       // 0..1 (m half)
    const int wn = warp & 3;        // 0..3 (n quarter)
    const int m0 = blockIdx.x * TM; // grid.x = 4 (m fastest -> B shared in L2)
    const int n0 = blockIdx.y * TN;

    // ---- cp.async source/dest mapping (per thread: 4 x 16B per stage) ----
    const int crow = tid >> 2;                  // 0..63
    const int cseg = tid & 3;                   // 0..3 (16B segment in 64B row)
    const __nv_bfloat16* gA = g_qb  + (size_t)(m0 + crow) * DDIM + cseg * 8;
    const __nv_bfloat16* gB = g_libb + (size_t)(n0 + crow) * DDIM + cseg * 8;
    const uint32_t sA = sbase + crow * ROWB + cseg * 16;

    // ---- ldmatrix smem addresses ----
    uint32_t aAddr[4], bAddr[2];
#pragma unroll
    for (int mi = 0; mi < 4; ++mi)
        aAddr[mi] = sbase + (64 * wm + 16 * mi + (lane & 15)) * ROWB + 16 * (lane >> 4);
#pragma unroll
    for (int bi = 0; bi < 2; ++bi)
        bAddr[bi] = sbase + MAT_BYTES
                  + (32 * wn + 16 * bi + ((lane & 7) + 8 * (lane >> 4))) * ROWB
                  + 16 * ((lane >> 3) & 1);

    float acc[4][4][4];
#pragma unroll
    for (int mi = 0; mi < 4; ++mi)
#pragma unroll
        for (int ni = 0; ni < 4; ++ni)
#pragma unroll
            for (int k = 0; k < 4; ++k) acc[mi][ni][k] = 0.f;

    auto load_stage = [&](int t, int stg) {
        const uint32_t so = sA + stg * STAGE_BYTES;
        const __nv_bfloat16* a = gA + t * KCH;
        const __nv_bfloat16* b = gB + t * KCH;
        cp16(so,                         a);
        cp16(so + HALF_TILE,             a + (size_t)64 * DDIM);
        cp16(so + MAT_BYTES,             b);
        cp16(so + MAT_BYTES + HALF_TILE, b + (size_t)64 * DDIM);
        cp_commit();
    };

    // prologue: stages 0..2
    load_stage(0, 0);
    load_stage(1, 1);
    load_stage(2, 2);

#pragma unroll 1
    for (int t = 0; t < NCHUNK; ++t) {
        cp_wait<2>();
        __syncthreads();
        if (t + 3 < NCHUNK) load_stage(t + 3, (t + 3) & (NSTG - 1));

        const uint32_t soff = (t & (NSTG - 1)) * STAGE_BYTES;
#pragma unroll
        for (int ks = 0; ks < 2; ++ks) {
            uint32_t af[4][4], bfr[2][4];
#pragma unroll
            for (int mi = 0; mi < 4; ++mi)
                ldm4(af[mi][0], af[mi][1], af[mi][2], af[mi][3],
                     aAddr[mi] + soff + 32 * ks);
#pragma unroll
            for (int bi = 0; bi < 2; ++bi)
                ldm4(bfr[bi][0], bfr[bi][1], bfr[bi][2], bfr[bi][3],
                     bAddr[bi] + soff + 32 * ks);
#pragma unroll
            for (int mi = 0; mi < 4; ++mi)
#pragma unroll
                for (int ni = 0; ni < 4; ++ni)
                    mma16816(acc[mi][ni], af[mi], &bfr[ni >> 1][(ni & 1) * 2]);
        }
    }

    // ---- epilogue: d2 = qsq + xsq - 2*dot ----
#pragma unroll
    for (int mi = 0; mi < 4; ++mi) {
        const int r0 = m0 + 64 * wm + 16 * mi + (lane >> 2);
        const float qs0 = g_qsq[r0];
        const float qs1 = g_qsq[r0 + 8];
#pragma unroll
        for (int ni = 0; ni < 4; ++ni) {
            const int c0 = n0 + 32 * wn + 8 * ni + 2 * (lane & 3);
            const float2 xs = *reinterpret_cast<const float2*>(&g_xsq[c0]);
            const float* c = acc[mi][ni];
            float2 o0, o1;
            o0.x = fmaf(-2.f, c[0], qs0 + xs.x);
            o0.y = fmaf(-2.f, c[1], qs0 + xs.y);
            o1.x = fmaf(-2.f, c[2], qs1 + xs.x);
            o1.y = fmaf(-2.f, c[3], qs1 + xs.y);
            *reinterpret_cast<float2*>(&g_d2[(size_t)r0 * NLIB + c0]) = o0;
            *reinterpret_cast<float2*>(&g_d2[(size_t)(r0 + 8) * NLIB + c0]) = o1;
        }
    }
}

// ---------------- top-16 candidate selection: one CTA per query ----------------
__global__ void topk_kernel() {
    const int q = blockIdx.x;
    const int tid = threadIdx.x;             // 256 threads
    const float* row = g_d2 + (size_t)q * NLIB;

    float lv[KCAND];
    int   li[KCAND];
#pragma unroll
    for (int s = 0; s < KCAND; ++s) { lv[s] = FLT_MAX; li[s] = 0x7FFFFFFF; }
    float th = FLT_MAX;

    for (int j = tid; j < NLIB; j += 256) {
        float v = row[j];
        if (v < th) {
            int p = KCAND - 1;
            while (p > 0 && lv[p - 1] > v) {
                lv[p] = lv[p - 1]; li[p] = li[p - 1]; --p;
            }
            lv[p] = v; li[p] = j;
            th = lv[KCAND - 1];
        }
    }

    __shared__ float sv[256 * KCAND];
    __shared__ int   si[256 * KCAND];
    __shared__ float rv[256];
    __shared__ int   ri[256];
    __shared__ int   rp[256];
#pragma unroll
    for (int s = 0; s < KCAND; ++s) {
        sv[tid * KCAND + s] = lv[s];
        si[tid * KCAND + s] = li[s];
    }
    __syncthreads();

    for (int r = 0; r < KCAND; ++r) {
        float bv = FLT_MAX; int bi = 0x7FFFFFFF; int bp = tid * KCAND;
#pragma unroll
        for (int s = 0; s < KCAND; ++s) {
            int p = tid * KCAND + s;
            float v = sv[p]; int ix = si[p];
            if (v < bv || (v == bv && ix < bi)) { bv = v; bi = ix; bp = p; }
        }
        rv[tid] = bv; ri[tid] = bi; rp[tid] = bp;
        __syncthreads();
        for (int s = 128; s > 0; s >>= 1) {
            if (tid < s) {
                float v2 = rv[tid + s]; int i2 = ri[tid + s];
                if (v2 < rv[tid] || (v2 == rv[tid] && i2 < ri[tid])) {
                    rv[tid] = v2; ri[tid] = i2; rp[tid] = rp[tid + s];
                }
            }
            __syncthreads();
        }
        if (tid == 0) {
            g_cand[q * KCAND + r] = ri[0];
            sv[rp[0]] = FLT_MAX;
            si[rp[0]] = 0x7FFFFFFF;
        }
        __syncthreads();
    }
}

// ---------------- exact fp32 rerank of 16 candidates ----------------
__global__ void rerank_kernel(const float* __restrict__ Qm, const float* __restrict__ Lm,
                              float* __restrict__ out, int out_size) {
    const int q = blockIdx.x;
    const int wid = threadIdx.x >> 5;
    const int lane = threadIdx.x & 31;
    __shared__ float cv[KCAND];
    __shared__ int   ci[KCAND];

    for (int c = wid; c < KCAND; c += 4) {
        int idx = g_cand[q * KCAND + c];
        const float4* xp = reinterpret_cast<const float4*>(Lm + (size_t)idx * DDIM);
        const float4* qp = reinterpret_cast<const float4*>(Qm + (size_t)q * DDIM);
        float dot = 0.f;
#pragma unroll
        for (int i = lane; i < DDIM / 4; i += 32) {
            float4 a = qp[i], b = xp[i];
            dot = fmaf(a.x, b.x, fmaf(a.y, b.y, fmaf(a.z, b.z, fmaf(a.w, b.w, dot))));
        }
#pragma unroll
        for (int o = 16; o; o >>= 1) dot += __shfl_xor_sync(0xffffffffu, dot, o);
        if (lane == 0) {
            cv[c] = fmaf(-2.f, dot, g_qsq[q] + g_xsq[idx]);
            ci[c] = idx;
        }
    }
    __syncthreads();
    if (threadIdx.x == 0) {
        for (int a = 1; a < KCAND; ++a) {
            float v = cv[a]; int ix = ci[a]; int b = a - 1;
            while (b >= 0 && (cv[b] > v || (cv[b] == v && ci[b] > ix))) {
                cv[b + 1] = cv[b]; ci[b + 1] = ci[b]; --b;
            }
            cv[b + 1] = v; ci[b + 1] = ix;
        }
        for (int r = 0; r < KOUT; ++r) {
            int o = q * KOUT + r;
            if (o < out_size) out[o] = cv[r];
            int o2 = QN * KOUT + q * KOUT + r;
            if (o2 < out_size) out[o2] = (float)ci[r];
        }
    }
}

// ---------------- launch ----------------
extern "C" void kernel_launch(void* const* d_in, const int* in_sizes, int n_in,
                              void* d_out, int out_size) {
    const float* query = (const float*)d_in[0];
    const float* lib   = (const float*)d_in[1];
    float* out = (float*)d_out;

    static int configured = 0;
    if (!configured) {
        cudaFuncSetAttribute(gemm_kernel,
                             cudaFuncAttributeMaxDynamicSharedMemorySize, SMEM_BYTES);
        configured = 1;
    }

    // fp32 -> bf16 conversion fused with exact fp32 row norms
    __nv_bfloat16 *qb, *lb;
    float *qsq, *xsq;
    cudaGetSymbolAddress((void**)&qb,  g_qb);
    cudaGetSymbolAddress((void**)&lb,  g_libb);
    cudaGetSymbolAddress((void**)&qsq, g_qsq);
    cudaGetSymbolAddress((void**)&xsq, g_xsq);
    convert_kernel<<<(QN * 32 + 255) / 256, 256>>>(query, qb, qsq, QN);
    convert_kernel<<<(NLIB * 32 + 255) / 256, 256>>>(lib, lb, xsq, NLIB);

    // approx distance matrix (single bf16 term, fp32 accumulate)
    dim3 grid(QN / TM, NLIB / TN);
    gemm_kernel<<<grid, 256, SMEM_BYTES>>>();

    // approx top-16, then exact fp32 rerank -> top-10
    topk_kernel<<<QN, 256>>>();
    rerank_kernel<<<QN, 128>>>(query, lib, out, out_size);
}